// round 15
// baseline (speedup 1.0000x reference)
#include <cuda_runtime.h>
#include <cuda_fp16.h>
#include <math.h>
#include <stdint.h>

// ---------------- problem constants ----------------
#define BATCH   32
#define HIMG    56
#define WIMG    56
#define CH      512
#define NHEAD   16
#define WS      7
#define SSH     3
#define HD      32
#define NWIN    49
#define NW_IMG  64
#define BN      (BATCH*NW_IMG)      // 2048 windows
#define MTOK    (BN*NWIN)           // 100352 tokens
#define HID     2048
#define SCALE   0.17677669529663687f
#define NN      (NWIN*NWIN)         // 2401

// ---------------- scratch ----------------
__device__ __align__(128) unsigned char g_R1[(size_t)MTOK * HID * 4];
__device__ __align__(128) unsigned char g_R2[(size_t)MTOK * CH * 2];

__device__ __align__(128) __half g_qkvT[3 * CH * CH];
__device__ __align__(128) __half g_projT[CH * CH];
__device__ __align__(128) __half g_fc1T[HID * CH];
__device__ __align__(128) __half g_fc2T[CH * HID];

// ---------------- helpers ----------------
__device__ __forceinline__ uint32_t smem_u32(const void* p) {
    uint32_t a;
    asm("{ .reg .u64 t; cvta.to.shared.u64 t, %1; cvt.u32.u64 %0, t; }" : "=r"(a) : "l"(p));
    return a;
}
#define CP16(dst, src) \
    asm volatile("cp.async.cg.shared.global [%0], [%1], 16;" :: "r"(dst), "l"(src))
#define CPCOMMIT() asm volatile("cp.async.commit_group;" ::: "memory")
#define CPWAIT1()  asm volatile("cp.async.wait_group 1;" ::: "memory")
#define CPWAIT0()  asm volatile("cp.async.wait_group 0;" ::: "memory")

#define LDSM4(r, a) \
    asm volatile("ldmatrix.sync.aligned.m8n8.x4.shared.b16 {%0,%1,%2,%3}, [%4];" \
        : "=r"((r)[0]), "=r"((r)[1]), "=r"((r)[2]), "=r"((r)[3]) : "r"(a))

__device__ __forceinline__ void mma_f16(float* c, const uint32_t* a, const uint32_t* b) {
    asm volatile("mma.sync.aligned.m16n8k16.row.col.f32.f16.f16.f32 "
        "{%0,%1,%2,%3}, {%4,%5,%6,%7}, {%8,%9}, {%0,%1,%2,%3};"
        : "+f"(c[0]), "+f"(c[1]), "+f"(c[2]), "+f"(c[3])
        : "r"(a[0]), "r"(a[1]), "r"(a[2]), "r"(a[3]), "r"(b[0]), "r"(b[1]));
}

// ---------------- unified prep kernel ----------------
__device__ __forceinline__ void wsplit_tile(const float* __restrict__ W, __half* __restrict__ oh,
                                            int K, int N, int bx, int by, float (*t)[33])
{
    int n0 = bx * 32, k0 = by * 32;
    int tx = threadIdx.x & 31, ty = threadIdx.x >> 5;
    #pragma unroll
    for (int i = ty; i < 32; i += 8)
        t[i][tx] = W[(size_t)(k0 + i) * N + n0 + tx];
    __syncthreads();
    #pragma unroll
    for (int i = ty; i < 32; i += 8)
        oh[(size_t)(n0 + i) * K + k0 + tx] = __float2half_rn(t[tx][i]);
}

// fused bias in MMA-fragment layout: fbf[s][wl*16 + f*4 + q], s = wi*16+h
__global__ __launch_bounds__(256)
void prep_kernel(const float* __restrict__ qkv_w, const float* __restrict__ proj_w,
                 const float* __restrict__ fc1_w, const float* __restrict__ fc2_w,
                 __half* __restrict__ qkvT, __half* __restrict__ projT,
                 __half* __restrict__ fc1T, __half* __restrict__ fc2T,
                 const float* __restrict__ table, const int* __restrict__ relidx,
                 const float* __restrict__ mask, float* __restrict__ fbf)
{
    __shared__ float t[32][33];
    int id = blockIdx.x;
    if (id < 768) {
        wsplit_tile(qkv_w, qkvT, CH, 3 * CH, id % 48, id / 48, t);
    } else if (id < 1024) {
        int s = id - 768;
        wsplit_tile(proj_w, projT, CH, CH, s % 16, s / 16, t);
    } else if (id < 2048) {
        int s = id - 1024;
        wsplit_tile(fc1_w, fc1T, CH, HID, s % 64, s / 64, t);
    } else if (id < 3072) {
        int s = id - 2048;
        wsplit_tile(fc2_w, fc2T, HID, CH, s % 16, s / 16, t);
    } else {
        int s = id - 3072;                 // 0..1023 = wi*16+h
        int wi = s >> 4, h = s & 15;
        const float* mrow = mask + (size_t)wi * NN;
        float* dst = fbf + (size_t)s * 4096;
        for (int i = threadIdx.x; i < 4096; i += 256) {
            int wl = i >> 4;               // wid*32+lane
            int f = (i >> 2) & 3, q = i & 3;
            int wid = wl >> 5, lane = wl & 31;
            int wm = wid & 3, wn = wid >> 2;
            int r = wm * 16 + (lane >> 2) + (q >= 2 ? 8 : 0);
            int c = wn * 32 + f * 8 + (lane & 3) * 2 + (q & 1);
            float v = -1e30f;
            if (r < NWIN && c < NWIN)
                v = table[relidx[r * NWIN + c] * NHEAD + h] + mrow[r * NWIN + c];
            dst[i] = v;
        }
    }
}

// ---------------- LayerNorm, warp-per-token ----------------
__global__ __launch_bounds__(128)
void ln_kernel(const float* __restrict__ x, const float* __restrict__ gamma,
               const float* __restrict__ beta, __half* __restrict__ oh, int mode)
{
    int warp = threadIdx.x >> 5, lane = threadIdx.x & 31;
    int tok = blockIdx.x * 4 + warp;
    int src;
    if (mode == 1) {
        int w = tok / NWIN, n = tok - w * NWIN;
        int b = w >> 6, wi = w & 63;
        int wh = wi >> 3, ww = wi & 7;
        int i = n / WS, j = n - i * WS;
        int hp = wh * WS + i, wp = ww * WS + j;
        int hs = hp + SSH; if (hs >= HIMG) hs -= HIMG;
        int ws_ = wp + SSH; if (ws_ >= WIMG) ws_ -= WIMG;
        src = b * (HIMG * WIMG) + hs * WIMG + ws_;
    } else {
        src = tok;
    }
    const float* xp = x + (size_t)src * CH;
    float4 v[4];
    float s = 0.0f, sq = 0.0f;
    #pragma unroll
    for (int k = 0; k < 4; ++k) {
        v[k] = *(const float4*)(xp + k * 128 + lane * 4);
        s  += v[k].x + v[k].y + v[k].z + v[k].w;
        sq += v[k].x*v[k].x + v[k].y*v[k].y + v[k].z*v[k].z + v[k].w*v[k].w;
    }
    #pragma unroll
    for (int off = 16; off; off >>= 1) {
        s  += __shfl_xor_sync(0xffffffffu, s, off);
        sq += __shfl_xor_sync(0xffffffffu, sq, off);
    }
    float mean = s * (1.0f / CH);
    float inv = rsqrtf(sq * (1.0f / CH) - mean * mean + 1e-5f);
    __half* op = oh + (size_t)tok * CH;
    #pragma unroll
    for (int k = 0; k < 4; ++k) {
        int c = k * 128 + lane * 4;
        float4 g4 = *(const float4*)(gamma + c);
        float4 b4 = *(const float4*)(beta + c);
        __half hh[4];
        hh[0] = __float2half_rn((v[k].x - mean) * inv * g4.x + b4.x);
        hh[1] = __float2half_rn((v[k].y - mean) * inv * g4.y + b4.y);
        hh[2] = __float2half_rn((v[k].z - mean) * inv * g4.z + b4.z);
        hh[3] = __float2half_rn((v[k].w - mean) * inv * g4.w + b4.w);
        *(uint2*)(op + c) = *(uint2*)hh;
    }
}

// ---------------- fp16 GEMM via mma.sync (R9, f32 accumulate) ----------------
#define OFF_B   16384
#define STG_SZ  32768
#define TGEMM_SMEM (3 * STG_SZ)

template <int EPI>
__global__ void __launch_bounds__(256, 2)
tgemm(const __half* __restrict__ Ah, const __half* __restrict__ Bh,
      const float* __restrict__ bias, float* __restrict__ C,
      __half* __restrict__ Ch, int M, int N, int K)
{
    extern __shared__ __align__(128) char smem[];
    uint32_t sb = smem_u32(smem);
    int tid = threadIdx.x, wid = tid >> 5, lane = tid & 31;
    int m0 = blockIdx.y << 7, n0 = blockIdx.x << 7;
    int wm = wid & 3, wn = wid >> 2;

    int ar = tid >> 1, ac = (tid & 1) * 4;
    const char* gA = (const char*)(Ah + (size_t)(m0 + ar) * K) + ac * 16;
    const char* gB = (const char*)(Bh + (size_t)(n0 + ar) * K) + ac * 16;
    uint32_t sw[4];
    #pragma unroll
    for (int j = 0; j < 4; ++j)
        sw[j] = (uint32_t)(ar * 128 + (((ac + j) ^ (ar & 7)) << 4));

    int arow = wm * 32 + (lane & 15);
    uint32_t aterm = (uint32_t)(arow * 128);
    int axor = arow & 7;
    int ac16 = lane >> 4;
    int brow = wn * 64 + ((lane >> 4) & 1) * 8 + (lane & 7);
    uint32_t bterm = (uint32_t)(brow * 128);
    int bxor = brow & 7;
    int bc16 = (lane >> 3) & 1;

    float acc[2][8][4];
    #pragma unroll
    for (int i = 0; i < 2; ++i)
        #pragma unroll
        for (int j = 0; j < 8; ++j)
            #pragma unroll
            for (int q = 0; q < 4; ++q) acc[i][j][q] = 0.0f;

    const int nch = K >> 6;

    #pragma unroll
    for (int pc = 0; pc < 2; ++pc) {
        uint32_t s = sb + pc * STG_SZ;
        size_t go = (size_t)pc * 128;
        #pragma unroll
        for (int j = 0; j < 4; ++j) {
            CP16(s + sw[j],         gA + go + j * 16);
            CP16(s + OFF_B + sw[j], gB + go + j * 16);
        }
        CPCOMMIT();
    }

    int buf = 0;
    for (int c = 0; c < nch; ++c) {
        if (c + 1 < nch) { CPWAIT1(); } else { CPWAIT0(); }
        __syncthreads();
        if (c + 2 < nch) {
            int b2 = buf + 2; if (b2 >= 3) b2 -= 3;
            uint32_t s = sb + b2 * STG_SZ;
            size_t go = (size_t)(c + 2) * 128;
            #pragma unroll
            for (int j = 0; j < 4; ++j) {
                CP16(s + sw[j],         gA + go + j * 16);
                CP16(s + OFF_B + sw[j], gB + go + j * 16);
            }
            CPCOMMIT();
        } else {
            CPCOMMIT();
        }

        uint32_t sS = sb + buf * STG_SZ;
        #pragma unroll
        for (int k16 = 0; k16 < 4; ++k16) {
            uint32_t ah[2][4];
            uint32_t aoff = aterm + ((uint32_t)((2 * k16 + ac16) ^ axor) << 4);
            LDSM4(ah[0], sS + aoff);
            LDSM4(ah[1], sS + aoff + 2048);
            uint32_t boff = bterm + ((uint32_t)((2 * k16 + bc16) ^ bxor) << 4);
            #pragma unroll
            for (int ng = 0; ng < 4; ++ng) {
                uint32_t bh[4];
                LDSM4(bh, sS + OFF_B + boff + ng * 2048);
                #pragma unroll
                for (int mt = 0; mt < 2; ++mt) {
                    mma_f16(acc[mt][2 * ng],     ah[mt], &bh[0]);
                    mma_f16(acc[mt][2 * ng + 1], ah[mt], &bh[2]);
                }
            }
        }
        if (++buf == 3) buf = 0;
    }

    int r0 = m0 + wm * 32 + (lane >> 2);
    int cb = n0 + wn * 64 + (lane & 3) * 2;
    #pragma unroll
    for (int mt = 0; mt < 2; ++mt) {
        #pragma unroll
        for (int n8 = 0; n8 < 8; ++n8) {
            int col = cb + n8 * 8;
            float2 bv = *(const float2*)(bias + col);
            #pragma unroll
            for (int rt = 0; rt < 2; ++rt) {
                int row = r0 + mt * 16 + rt * 8;
                float vx = acc[mt][n8][rt * 2]     + bv.x;
                float vy = acc[mt][n8][rt * 2 + 1] + bv.y;
                if (EPI == 0) {
                    float2 r = {vx, vy};
                    *(float2*)(C + (size_t)row * N + col) = r;
                } else if (EPI == 1) {
                    float gx = 0.5f * vx * (1.0f + erff(vx * 0.70710678118654752f));
                    float gy = 0.5f * vy * (1.0f + erff(vy * 0.70710678118654752f));
                    __half hh[2];
                    hh[0] = __float2half_rn(gx);
                    hh[1] = __float2half_rn(gy);
                    *(uint32_t*)(Ch + (size_t)row * N + col) = *(uint32_t*)hh;
                } else if (EPI == 2) {
                    float* cp = C + (size_t)row * N + col;
                    float2 old = *(const float2*)cp;
                    float2 r = {vx + old.x, vy + old.y};
                    *(float2*)cp = r;
                } else {
                    __half hh[2];
                    hh[0] = __float2half_rn(vx);
                    hh[1] = __float2half_rn(vy);
                    *(uint32_t*)(Ch + (size_t)row * N + col) = *(uint32_t*)hh;
                }
            }
        }
    }
}

// ---------------- HMMA attention v4: fragment-layout bias, register softmax ----------------
#define SQR 40   // q/k stride (halves)
#define SPR 72   // v^T stride (halves)
__global__ __launch_bounds__(256)
void attn_kernel(const __half* __restrict__ qkv, const float* __restrict__ fbf,
                 __half* __restrict__ oh)
{
    __shared__ __half sq[64 * SQR], sk[64 * SQR], svt[32 * SPR];
    __shared__ float red[64][2][2];
    __shared__ float pacc[4][16][34];

    int bh = blockIdx.x;
    int b = bh >> 4, h = bh & 15;
    int tid = threadIdx.x, wid = tid >> 5, lane = tid & 31;

    // zero q/k padding rows 49..63 (5 uint4 per row) and v^T padding cols
    for (int idx = tid; idx < 150; idx += 256) {
        int arr = idx / 75, rem = idx - arr * 75;
        int row = 49 + rem / 5, c8 = (rem % 5) * 8;
        __half* base = arr ? sk : sq;
        *(uint4*)&base[row * SQR + c8] = make_uint4(0, 0, 0, 0);
    }
    for (int idx = tid; idx < 32 * 15; idx += 256) {
        int d = idx / 15, m = 49 + idx % 15;
        svt[d * SPR + m] = __float2half_rn(0.0f);
    }
    for (int idx = tid; idx < NWIN * 4; idx += 256) {
        int n = idx >> 2, c8 = (idx & 3) << 3;
        size_t base = (size_t)(b * NWIN + n) * (3 * CH) + h * HD + c8;
        *(uint4*)&sq[n * SQR + c8] = *(const uint4*)(qkv + base);
        *(uint4*)&sk[n * SQR + c8] = *(const uint4*)(qkv + base + CH);
    }
    for (int idx = tid; idx < NWIN * 16; idx += 256) {
        int m = idx >> 4, d = (idx & 15) * 2;
        __half2 v = *(const __half2*)(qkv + (size_t)(b * NWIN + m) * (3 * CH) + 2 * CH + h * HD + d);
        svt[d * SPR + m]       = __low2half(v);
        svt[(d + 1) * SPR + m] = __high2half(v);
    }
    __syncthreads();

    int wm = wid & 3, wn = wid >> 2;
    int r1 = wm * 16 + (lane >> 2), r2 = r1 + 8;

    // ---- S = Q @ K^T ----
    float acc[4][4];
    #pragma unroll
    for (int f = 0; f < 4; ++f)
        #pragma unroll
        for (int q = 0; q < 4; ++q) acc[f][q] = 0.0f;
    {
        uint32_t aQ = smem_u32(sq) + (uint32_t)((wm * 16 + (lane & 15)) * (SQR * 2)) + (uint32_t)((lane >> 4) * 16);
        uint32_t bK = smem_u32(sk) + (uint32_t)((wn * 32 + ((lane >> 4) & 1) * 8 + (lane & 7)) * (SQR * 2))
                    + (uint32_t)(((lane >> 3) & 1) * 16);
        #pragma unroll
        for (int ks = 0; ks < 2; ++ks) {
            uint32_t af[4];
            LDSM4(af, aQ + ks * 32);
            #pragma unroll
            for (int half = 0; half < 2; ++half) {
                uint32_t bf[4];
                LDSM4(bf, bK + half * 16 * (SQR * 2) + ks * 32);
                mma_f16(acc[half * 2 + 0], af, &bf[0]);
                mma_f16(acc[half * 2 + 1], af, &bf[2]);
            }
        }
    }

    // ---- fragment-layout bias: 4 coalesced float4 loads ----
    const float4* fbp = (const float4*)(fbf + (size_t)(((b & 63) << 4) + h) * 4096 + (size_t)tid * 16);
    float v1r[8], v2r[8];
    #pragma unroll
    for (int f = 0; f < 4; ++f) {
        float4 fv = fbp[f];
        v1r[f * 2]     = acc[f][0] * SCALE + fv.x;
        v1r[f * 2 + 1] = acc[f][1] * SCALE + fv.y;
        v2r[f * 2]     = acc[f][2] * SCALE + fv.z;
        v2r[f * 2 + 1] = acc[f][3] * SCALE + fv.w;
    }

    // ---- per-warp partial softmax ----
    float m1 = -1e30f, m2 = -1e30f;
    #pragma unroll
    for (int j = 0; j < 8; ++j) { m1 = fmaxf(m1, v1r[j]); m2 = fmaxf(m2, v2r[j]); }
    m1 = fmaxf(m1, __shfl_xor_sync(0xffffffffu, m1, 1));
    m1 = fmaxf(m1, __shfl_xor_sync(0xffffffffu, m1, 2));
    m2 = fmaxf(m2, __shfl_xor_sync(0xffffffffu, m2, 1));
    m2 = fmaxf(m2, __shfl_xor_sync(0xffffffffu, m2, 2));
    float s1 = 0.0f, s2 = 0.0f;
    #pragma unroll
    for (int j = 0; j < 8; ++j) {
        v1r[j] = expf(v1r[j] - m1); s1 += v1r[j];
        v2r[j] = expf(v2r[j] - m2); s2 += v2r[j];
    }
    s1 += __shfl_xor_sync(0xffffffffu, s1, 1);
    s1 += __shfl_xor_sync(0xffffffffu, s1, 2);
    s2 += __shfl_xor_sync(0xffffffffu, s2, 1);
    s2 += __shfl_xor_sync(0xffffffffu, s2, 2);
    if ((lane & 3) == 0) {
        red[r1][wn][0] = m1; red[r1][wn][1] = s1;
        red[r2][wn][0] = m2; red[r2][wn][1] = s2;
    }
    __syncthreads();

    float M1 = fmaxf(red[r1][0][0], red[r1][1][0]);
    float S1 = red[r1][0][1] * expf(red[r1][0][0] - M1) + red[r1][1][1] * expf(red[r1][1][0] - M1);
    float fac1 = expf(m1 - M1) / S1;
    float M2 = fmaxf(red[r2][0][0], red[r2][1][0]);
    float S2 = red[r2][0][1] * expf(red[r2][0][0] - M2) + red[r2][1][1] * expf(red[r2][1][0] - M2);
    float fac2 = expf(m2 - M2) / S2;

    // ---- O_partial = P @ V ----
    float acc2[4][4];
    #pragma unroll
    for (int nt = 0; nt < 4; ++nt)
        #pragma unroll
        for (int q = 0; q < 4; ++q) acc2[nt][q] = 0.0f;
    {
        uint32_t vb = smem_u32(svt);
        #pragma unroll
        for (int t = 0; t < 2; ++t) {
            uint32_t ap[4];
            __half2 h0 = __floats2half2_rn(v1r[4 * t]     * fac1, v1r[4 * t + 1] * fac1);
            __half2 h1 = __floats2half2_rn(v2r[4 * t]     * fac2, v2r[4 * t + 1] * fac2);
            __half2 h2 = __floats2half2_rn(v1r[4 * t + 2] * fac1, v1r[4 * t + 3] * fac1);
            __half2 h3 = __floats2half2_rn(v2r[4 * t + 2] * fac2, v2r[4 * t + 3] * fac2);
            ap[0] = *(uint32_t*)&h0; ap[1] = *(uint32_t*)&h1;
            ap[2] = *(uint32_t*)&h2; ap[3] = *(uint32_t*)&h3;
            #pragma unroll
            for (int dt = 0; dt < 2; ++dt) {
                uint32_t bf[4];
                uint32_t addr = vb + (uint32_t)((dt * 16 + ((lane >> 4) & 1) * 8 + (lane & 7)) * (SPR * 2))
                              + (uint32_t)(((lane >> 3) & 1) * 16) + (uint32_t)(wn * 64 + t * 32);
                LDSM4(bf, addr);
                mma_f16(acc2[dt * 2 + 0], ap, &bf[0]);
                mma_f16(acc2[dt * 2 + 1], ap, &bf[2]);
            }
        }
    }

    if (wn == 1) {
        #pragma unroll
        for (int nt = 0; nt < 4; ++nt) {
            int d = nt * 8 + (lane & 3) * 2;
            *(float2*)&pacc[wm][lane >> 2][d]       = make_float2(acc2[nt][0], acc2[nt][1]);
            *(float2*)&pacc[wm][(lane >> 2) + 8][d] = make_float2(acc2[nt][2], acc2[nt][3]);
        }
    }
    __syncthreads();
    if (wn == 0) {
        #pragma unroll
        for (int nt = 0; nt < 4; ++nt) {
            int d = nt * 8 + (lane & 3) * 2;
            float2 p1 = *(const float2*)&pacc[wm][lane >> 2][d];
            float2 p2 = *(const float2*)&pacc[wm][(lane >> 2) + 8][d];
            if (r1 < NWIN)
                *(__half2*)(oh + (size_t)(b * NWIN + r1) * CH + h * HD + d) =
                    __floats2half2_rn(acc2[nt][0] + p1.x, acc2[nt][1] + p1.y);
            if (r2 < NWIN)
                *(__half2*)(oh + (size_t)(b * NWIN + r2) * CH + h * HD + d) =
                    __floats2half2_rn(acc2[nt][2] + p2.x, acc2[nt][3] + p2.y);
        }
    }
}

// ---------------- fused: reverse+roll+residual -> out, LN2 -> yh ----------------
__global__ __launch_bounds__(128)
void fuse2_kernel(const float* __restrict__ x, const __half* __restrict__ projh,
                  const float* __restrict__ gamma, const float* __restrict__ beta,
                  float* __restrict__ out, __half* __restrict__ yh)
{
    int warp = threadIdx.x >> 5, lane = threadIdx.x & 31;
    int tok = blockIdx.x * 4 + warp;
    int b = tok / (HIMG * WIMG);
    int rem = tok - b * (HIMG * WIMG);
    int hp0 = rem / WIMG, wp0 = rem - hp0 * WIMG;
    int hp = hp0 - SSH; if (hp < 0) hp += HIMG;
    int wp = wp0 - SSH; if (wp < 0) wp += WIMG;
    int wh = hp / WS, i = hp - wh * WS;
    int ww = wp / WS, j = wp - ww * WS;
    int src = (b * NW_IMG + wh * 8 + ww) * NWIN + i * WS + j;

    const float* xp = x + (size_t)tok * CH;
    const __half* pp = projh + (size_t)src * CH;
    float* op = out + (size_t)tok * CH;

    float4 a[4];
    float s = 0.0f, sq = 0.0f;
    #pragma unroll
    for (int k = 0; k < 4; ++k) {
        int c = k * 128 + lane * 4;
        a[k] = *(const float4*)(xp + c);
        union { uint2 u; __half hx[4]; } ph;
        ph.u = *(const uint2*)(pp + c);
        a[k].x += __half2float(ph.hx[0]);
        a[k].y += __half2float(ph.hx[1]);
        a[k].z += __half2float(ph.hx[2]);
        a[k].w += __half2float(ph.hx[3]);
        *(float4*)(op + c) = a[k];
        s  += a[k].x + a[k].y + a[k].z + a[k].w;
        sq += a[k].x*a[k].x + a[k].y*a[k].y + a[k].z*a[k].z + a[k].w*a[k].w;
    }
    #pragma unroll
    for (int off = 16; off; off >>= 1) {
        s  += __shfl_xor_sync(0xffffffffu, s, off);
        sq += __shfl_xor_sync(0xffffffffu, sq, off);
    }
    float mean = s * (1.0f / CH);
    float inv = rsqrtf(sq * (1.0f / CH) - mean * mean + 1e-5f);
    __half* yp = yh + (size_t)tok * CH;
    #pragma unroll
    for (int k = 0; k < 4; ++k) {
        int c = k * 128 + lane * 4;
        float4 g4 = *(const float4*)(gamma + c);
        float4 b4 = *(const float4*)(beta + c);
        __half hh[4];
        hh[0] = __float2half_rn((a[k].x - mean) * inv * g4.x + b4.x);
        hh[1] = __float2half_rn((a[k].y - mean) * inv * g4.y + b4.y);
        hh[2] = __float2half_rn((a[k].z - mean) * inv * g4.z + b4.z);
        hh[3] = __float2half_rn((a[k].w - mean) * inv * g4.w + b4.w);
        *(uint2*)(yp + c) = *(uint2*)hh;
    }
}

// ---------------- launcher ----------------
extern "C" void kernel_launch(void* const* d_in, const int* in_sizes, int n_in,
                              void* d_out, int out_size)
{
    const float* x        = (const float*)d_in[0];
    const float* norm1_g  = (const float*)d_in[1];
    const float* norm1_b  = (const float*)d_in[2];
    const float* qkv_w    = (const float*)d_in[3];
    const float* qkv_b    = (const float*)d_in[4];
    const float* rel_tab  = (const float*)d_in[5];
    const float* proj_w   = (const float*)d_in[6];
    const float* proj_b   = (const float*)d_in[7];
    const float* norm2_g  = (const float*)d_in[8];
    const float* norm2_b  = (const float*)d_in[9];
    const float* fc1_w    = (const float*)d_in[10];
    const float* fc1_b    = (const float*)d_in[11];
    const float* fc2_w    = (const float*)d_in[12];
    const float* fc2_b    = (const float*)d_in[13];
    const int*   rel_idx  = (const int*)d_in[14];
    const float* attn_msk = (const float*)d_in[15];
    float* out = (float*)d_out;

    unsigned char *R1, *R2;
    cudaGetSymbolAddress((void**)&R1, g_R1);
    cudaGetSymbolAddress((void**)&R2, g_R2);
    __half *qkvT, *projT, *fc1T, *fc2T;
    cudaGetSymbolAddress((void**)&qkvT, g_qkvT);
    cudaGetSymbolAddress((void**)&projT, g_projT);
    cudaGetSymbolAddress((void**)&fc1T, g_fc1T);
    cudaGetSymbolAddress((void**)&fc2T, g_fc2T);

    __half* qkv   = (__half*)R1;
    __half* projh = (__half*)(R1 + (size_t)MTOK * 3 * CH * 2);
    float* fbf    = (float*)(R1 + (size_t)600 * 1024 * 1024);   // 16.8MB fragment-layout bias
    __half* hid   = (__half*)R1;
    __half* act   = (__half*)R2;

    cudaFuncSetAttribute(tgemm<0>, cudaFuncAttributeMaxDynamicSharedMemorySize, TGEMM_SMEM);
    cudaFuncSetAttribute(tgemm<1>, cudaFuncAttributeMaxDynamicSharedMemorySize, TGEMM_SMEM);
    cudaFuncSetAttribute(tgemm<2>, cudaFuncAttributeMaxDynamicSharedMemorySize, TGEMM_SMEM);
    cudaFuncSetAttribute(tgemm<3>, cudaFuncAttributeMaxDynamicSharedMemorySize, TGEMM_SMEM);

    // 0) unified prep
    prep_kernel<<<4096, 256>>>(qkv_w, proj_w, fc1_w, fc2_w, qkvT, projT, fc1T, fc2T,
                               rel_tab, rel_idx, attn_msk, fbf);

    // 1) LN1 + shift + window partition
    ln_kernel<<<MTOK / 4, 128>>>(x, norm1_g, norm1_b, act, 1);

    // 2) QKV GEMM -> fp16
    tgemm<3><<<dim3(3 * CH / 128, MTOK / 128), 256, TGEMM_SMEM>>>(
        act, qkvT, qkv_b, nullptr, qkv, MTOK, 3 * CH, CH);

    // 3) attention
    attn_kernel<<<BN * NHEAD, 256>>>(qkv, fbf, act);

    // 4) proj GEMM -> fp16
    tgemm<3><<<dim3(CH / 128, MTOK / 128), 256, TGEMM_SMEM>>>(
        act, projT, proj_b, nullptr, projh, MTOK, CH, CH);

    // 5+6) reverse + residual -> d_out, fused LN2
    fuse2_kernel<<<MTOK / 4, 128>>>(x, projh, norm2_g, norm2_b, out, act);

    // 7) FC1 + GELU -> fp16 hid
    tgemm<1><<<dim3(HID / 128, MTOK / 128), 256, TGEMM_SMEM>>>(
        act, fc1T, fc1_b, nullptr, hid, MTOK, HID, CH);

    // 8) FC2 + residual into d_out
    tgemm<2><<<dim3(CH / 128, MTOK / 128), 256, TGEMM_SMEM>>>(
        hid, fc2T, fc2_b, out, nullptr, MTOK, CH, HID);

    (void)in_sizes; (void)n_in; (void)out_size;
}

// round 16
// speedup vs baseline: 1.0231x; 1.0231x over previous
#include <cuda_runtime.h>
#include <cuda_fp16.h>
#include <math.h>
#include <stdint.h>

// ---------------- problem constants ----------------
#define BATCH   32
#define HIMG    56
#define WIMG    56
#define CH      512
#define NHEAD   16
#define WS      7
#define SSH     3
#define HD      32
#define NWIN    49
#define NW_IMG  64
#define BN      (BATCH*NW_IMG)      // 2048 windows
#define MTOK    (BN*NWIN)           // 100352 tokens
#define HID     2048
#define SCALE   0.17677669529663687f
#define NN      (NWIN*NWIN)         // 2401

// ---------------- scratch ----------------
__device__ __align__(128) unsigned char g_R1[(size_t)MTOK * HID * 4];
__device__ __align__(128) unsigned char g_R2[(size_t)MTOK * CH * 2];

__device__ __align__(128) __half g_qkvT[3 * CH * CH];
__device__ __align__(128) __half g_projT[CH * CH];
__device__ __align__(128) __half g_fc1T[HID * CH];
__device__ __align__(128) __half g_fc2T[CH * HID];

// ---------------- helpers ----------------
__device__ __forceinline__ uint32_t smem_u32(const void* p) {
    uint32_t a;
    asm("{ .reg .u64 t; cvta.to.shared.u64 t, %1; cvt.u32.u64 %0, t; }" : "=r"(a) : "l"(p));
    return a;
}
#define CP16(dst, src) \
    asm volatile("cp.async.cg.shared.global [%0], [%1], 16;" :: "r"(dst), "l"(src))
#define CPCOMMIT() asm volatile("cp.async.commit_group;" ::: "memory")
#define CPWAIT1()  asm volatile("cp.async.wait_group 1;" ::: "memory")
#define CPWAIT0()  asm volatile("cp.async.wait_group 0;" ::: "memory")

#define LDSM4(r, a) \
    asm volatile("ldmatrix.sync.aligned.m8n8.x4.shared.b16 {%0,%1,%2,%3}, [%4];" \
        : "=r"((r)[0]), "=r"((r)[1]), "=r"((r)[2]), "=r"((r)[3]) : "r"(a))

#define LDSM4T(r, a) \
    asm volatile("ldmatrix.sync.aligned.m8n8.x4.trans.shared.b16 {%0,%1,%2,%3}, [%4];" \
        : "=r"((r)[0]), "=r"((r)[1]), "=r"((r)[2]), "=r"((r)[3]) : "r"(a))

__device__ __forceinline__ void mma_f16(float* c, const uint32_t* a, const uint32_t* b) {
    asm volatile("mma.sync.aligned.m16n8k16.row.col.f32.f16.f16.f32 "
        "{%0,%1,%2,%3}, {%4,%5,%6,%7}, {%8,%9}, {%0,%1,%2,%3};"
        : "+f"(c[0]), "+f"(c[1]), "+f"(c[2]), "+f"(c[3])
        : "r"(a[0]), "r"(a[1]), "r"(a[2]), "r"(a[3]), "r"(b[0]), "r"(b[1]));
}

// ---------------- unified prep kernel ----------------
__device__ __forceinline__ void wsplit_tile(const float* __restrict__ W, __half* __restrict__ oh,
                                            int K, int N, int bx, int by, float (*t)[33])
{
    int n0 = bx * 32, k0 = by * 32;
    int tx = threadIdx.x & 31, ty = threadIdx.x >> 5;
    #pragma unroll
    for (int i = ty; i < 32; i += 8)
        t[i][tx] = W[(size_t)(k0 + i) * N + n0 + tx];
    __syncthreads();
    #pragma unroll
    for (int i = ty; i < 32; i += 8)
        oh[(size_t)(n0 + i) * K + k0 + tx] = __float2half_rn(t[tx][i]);
}

// fused bias in MMA-fragment layout: fbf[s][wl*16 + f*4 + q], s = wi*16+h
__global__ __launch_bounds__(256)
void prep_kernel(const float* __restrict__ qkv_w, const float* __restrict__ proj_w,
                 const float* __restrict__ fc1_w, const float* __restrict__ fc2_w,
                 __half* __restrict__ qkvT, __half* __restrict__ projT,
                 __half* __restrict__ fc1T, __half* __restrict__ fc2T,
                 const float* __restrict__ table, const int* __restrict__ relidx,
                 const float* __restrict__ mask, float* __restrict__ fbf)
{
    __shared__ float t[32][33];
    int id = blockIdx.x;
    if (id < 768) {
        wsplit_tile(qkv_w, qkvT, CH, 3 * CH, id % 48, id / 48, t);
    } else if (id < 1024) {
        int s = id - 768;
        wsplit_tile(proj_w, projT, CH, CH, s % 16, s / 16, t);
    } else if (id < 2048) {
        int s = id - 1024;
        wsplit_tile(fc1_w, fc1T, CH, HID, s % 64, s / 64, t);
    } else if (id < 3072) {
        int s = id - 2048;
        wsplit_tile(fc2_w, fc2T, HID, CH, s % 16, s / 16, t);
    } else {
        int s = id - 3072;
        int wi = s >> 4, h = s & 15;
        const float* mrow = mask + (size_t)wi * NN;
        float* dst = fbf + (size_t)s * 4096;
        for (int i = threadIdx.x; i < 4096; i += 256) {
            int wl = i >> 4;
            int f = (i >> 2) & 3, q = i & 3;
            int wid = wl >> 5, lane = wl & 31;
            int wm = wid & 3, wn = wid >> 2;
            int r = wm * 16 + (lane >> 2) + (q >= 2 ? 8 : 0);
            int c = wn * 32 + f * 8 + (lane & 3) * 2 + (q & 1);
            float v = -1e30f;
            if (r < NWIN && c < NWIN)
                v = table[relidx[r * NWIN + c] * NHEAD + h] + mrow[r * NWIN + c];
            dst[i] = v;
        }
    }
}

// ---------------- LayerNorm, warp-per-token ----------------
__global__ __launch_bounds__(128)
void ln_kernel(const float* __restrict__ x, const float* __restrict__ gamma,
               const float* __restrict__ beta, __half* __restrict__ oh, int mode)
{
    int warp = threadIdx.x >> 5, lane = threadIdx.x & 31;
    int tok = blockIdx.x * 4 + warp;
    int src;
    if (mode == 1) {
        int w = tok / NWIN, n = tok - w * NWIN;
        int b = w >> 6, wi = w & 63;
        int wh = wi >> 3, ww = wi & 7;
        int i = n / WS, j = n - i * WS;
        int hp = wh * WS + i, wp = ww * WS + j;
        int hs = hp + SSH; if (hs >= HIMG) hs -= HIMG;
        int ws_ = wp + SSH; if (ws_ >= WIMG) ws_ -= WIMG;
        src = b * (HIMG * WIMG) + hs * WIMG + ws_;
    } else {
        src = tok;
    }
    const float* xp = x + (size_t)src * CH;
    float4 v[4];
    float s = 0.0f, sq = 0.0f;
    #pragma unroll
    for (int k = 0; k < 4; ++k) {
        v[k] = *(const float4*)(xp + k * 128 + lane * 4);
        s  += v[k].x + v[k].y + v[k].z + v[k].w;
        sq += v[k].x*v[k].x + v[k].y*v[k].y + v[k].z*v[k].z + v[k].w*v[k].w;
    }
    #pragma unroll
    for (int off = 16; off; off >>= 1) {
        s  += __shfl_xor_sync(0xffffffffu, s, off);
        sq += __shfl_xor_sync(0xffffffffu, sq, off);
    }
    float mean = s * (1.0f / CH);
    float inv = rsqrtf(sq * (1.0f / CH) - mean * mean + 1e-5f);
    __half* op = oh + (size_t)tok * CH;
    #pragma unroll
    for (int k = 0; k < 4; ++k) {
        int c = k * 128 + lane * 4;
        float4 g4 = *(const float4*)(gamma + c);
        float4 b4 = *(const float4*)(beta + c);
        __half hh[4];
        hh[0] = __float2half_rn((v[k].x - mean) * inv * g4.x + b4.x);
        hh[1] = __float2half_rn((v[k].y - mean) * inv * g4.y + b4.y);
        hh[2] = __float2half_rn((v[k].z - mean) * inv * g4.z + b4.z);
        hh[3] = __float2half_rn((v[k].w - mean) * inv * g4.w + b4.w);
        *(uint2*)(op + c) = *(uint2*)hh;
    }
}

// ---------------- fp16 GEMM via mma.sync (R9, f32 accumulate) ----------------
#define OFF_B   16384
#define STG_SZ  32768
#define TGEMM_SMEM (3 * STG_SZ)

template <int EPI>
__global__ void __launch_bounds__(256, 2)
tgemm(const __half* __restrict__ Ah, const __half* __restrict__ Bh,
      const float* __restrict__ bias, float* __restrict__ C,
      __half* __restrict__ Ch, int M, int N, int K)
{
    extern __shared__ __align__(128) char smem[];
    uint32_t sb = smem_u32(smem);
    int tid = threadIdx.x, wid = tid >> 5, lane = tid & 31;
    int m0 = blockIdx.y << 7, n0 = blockIdx.x << 7;
    int wm = wid & 3, wn = wid >> 2;

    int ar = tid >> 1, ac = (tid & 1) * 4;
    const char* gA = (const char*)(Ah + (size_t)(m0 + ar) * K) + ac * 16;
    const char* gB = (const char*)(Bh + (size_t)(n0 + ar) * K) + ac * 16;
    uint32_t sw[4];
    #pragma unroll
    for (int j = 0; j < 4; ++j)
        sw[j] = (uint32_t)(ar * 128 + (((ac + j) ^ (ar & 7)) << 4));

    int arow = wm * 32 + (lane & 15);
    uint32_t aterm = (uint32_t)(arow * 128);
    int axor = arow & 7;
    int ac16 = lane >> 4;
    int brow = wn * 64 + ((lane >> 4) & 1) * 8 + (lane & 7);
    uint32_t bterm = (uint32_t)(brow * 128);
    int bxor = brow & 7;
    int bc16 = (lane >> 3) & 1;

    float acc[2][8][4];
    #pragma unroll
    for (int i = 0; i < 2; ++i)
        #pragma unroll
        for (int j = 0; j < 8; ++j)
            #pragma unroll
            for (int q = 0; q < 4; ++q) acc[i][j][q] = 0.0f;

    const int nch = K >> 6;

    #pragma unroll
    for (int pc = 0; pc < 2; ++pc) {
        uint32_t s = sb + pc * STG_SZ;
        size_t go = (size_t)pc * 128;
        #pragma unroll
        for (int j = 0; j < 4; ++j) {
            CP16(s + sw[j],         gA + go + j * 16);
            CP16(s + OFF_B + sw[j], gB + go + j * 16);
        }
        CPCOMMIT();
    }

    int buf = 0;
    for (int c = 0; c < nch; ++c) {
        if (c + 1 < nch) { CPWAIT1(); } else { CPWAIT0(); }
        __syncthreads();
        if (c + 2 < nch) {
            int b2 = buf + 2; if (b2 >= 3) b2 -= 3;
            uint32_t s = sb + b2 * STG_SZ;
            size_t go = (size_t)(c + 2) * 128;
            #pragma unroll
            for (int j = 0; j < 4; ++j) {
                CP16(s + sw[j],         gA + go + j * 16);
                CP16(s + OFF_B + sw[j], gB + go + j * 16);
            }
            CPCOMMIT();
        } else {
            CPCOMMIT();
        }

        uint32_t sS = sb + buf * STG_SZ;
        #pragma unroll
        for (int k16 = 0; k16 < 4; ++k16) {
            uint32_t ah[2][4];
            uint32_t aoff = aterm + ((uint32_t)((2 * k16 + ac16) ^ axor) << 4);
            LDSM4(ah[0], sS + aoff);
            LDSM4(ah[1], sS + aoff + 2048);
            uint32_t boff = bterm + ((uint32_t)((2 * k16 + bc16) ^ bxor) << 4);
            #pragma unroll
            for (int ng = 0; ng < 4; ++ng) {
                uint32_t bh[4];
                LDSM4(bh, sS + OFF_B + boff + ng * 2048);
                #pragma unroll
                for (int mt = 0; mt < 2; ++mt) {
                    mma_f16(acc[mt][2 * ng],     ah[mt], &bh[0]);
                    mma_f16(acc[mt][2 * ng + 1], ah[mt], &bh[2]);
                }
            }
        }
        if (++buf == 3) buf = 0;
    }

    int r0 = m0 + wm * 32 + (lane >> 2);
    int cb = n0 + wn * 64 + (lane & 3) * 2;
    #pragma unroll
    for (int mt = 0; mt < 2; ++mt) {
        #pragma unroll
        for (int n8 = 0; n8 < 8; ++n8) {
            int col = cb + n8 * 8;
            float2 bv = *(const float2*)(bias + col);
            #pragma unroll
            for (int rt = 0; rt < 2; ++rt) {
                int row = r0 + mt * 16 + rt * 8;
                float vx = acc[mt][n8][rt * 2]     + bv.x;
                float vy = acc[mt][n8][rt * 2 + 1] + bv.y;
                if (EPI == 0) {
                    float2 r = {vx, vy};
                    *(float2*)(C + (size_t)row * N + col) = r;
                } else if (EPI == 1) {
                    float gx = 0.5f * vx * (1.0f + erff(vx * 0.70710678118654752f));
                    float gy = 0.5f * vy * (1.0f + erff(vy * 0.70710678118654752f));
                    __half hh[2];
                    hh[0] = __float2half_rn(gx);
                    hh[1] = __float2half_rn(gy);
                    *(uint32_t*)(Ch + (size_t)row * N + col) = *(uint32_t*)hh;
                } else if (EPI == 2) {
                    float* cp = C + (size_t)row * N + col;
                    float2 old = *(const float2*)cp;
                    float2 r = {vx + old.x, vy + old.y};
                    *(float2*)cp = r;
                } else {
                    __half hh[2];
                    hh[0] = __float2half_rn(vx);
                    hh[1] = __float2half_rn(vy);
                    *(uint32_t*)(Ch + (size_t)row * N + col) = *(uint32_t*)hh;
                }
            }
        }
    }
}

// ---------------- HMMA attention v5: cp.async loads + ldmatrix.trans V ----------------
#define SQR 40   // q/k/v row stride (halves) = 80B
__global__ __launch_bounds__(256)
void attn_kernel(const __half* __restrict__ qkv, const float* __restrict__ fbf,
                 __half* __restrict__ oh)
{
    __shared__ __half sq[64 * SQR], sk[64 * SQR], sv[64 * SQR];
    __shared__ float red[64][2][2];
    __shared__ float pacc[4][16][34];

    int bh = blockIdx.x;
    int b = bh >> 4, h = bh & 15;
    int tid = threadIdx.x, wid = tid >> 5, lane = tid & 31;

    // zero padding rows 49..63 for q, k, v (15 rows x 4 uint4 x 3 arrays)
    for (int idx = tid; idx < 180; idx += 256) {
        int arr = idx / 60, rem = idx - arr * 60;
        int row = 49 + (rem >> 2), c8 = (rem & 3) << 3;
        __half* base = (arr == 0) ? sq : (arr == 1) ? sk : sv;
        *(uint4*)&base[row * SQR + c8] = make_uint4(0, 0, 0, 0);
    }
    // cp.async q/k/v rows (49 x 4 x 16B each)
    {
        uint32_t sqa = smem_u32(sq), ska = smem_u32(sk), sva = smem_u32(sv);
        for (int idx = tid; idx < 588; idx += 256) {
            int arr = idx / 196, rem = idx - arr * 196;
            int n = rem >> 2, c8 = (rem & 3) << 3;
            const __half* src = qkv + (size_t)(b * NWIN + n) * (3 * CH) + arr * CH + h * HD + c8;
            uint32_t dst = ((arr == 0) ? sqa : (arr == 1) ? ska : sva)
                         + (uint32_t)((n * SQR + c8) * 2);
            CP16(dst, src);
        }
        CPCOMMIT();
        CPWAIT0();
    }
    __syncthreads();

    int wm = wid & 3, wn = wid >> 2;
    int r1 = wm * 16 + (lane >> 2), r2 = r1 + 8;

    // ---- S = Q @ K^T ----
    float acc[4][4];
    #pragma unroll
    for (int f = 0; f < 4; ++f)
        #pragma unroll
        for (int q = 0; q < 4; ++q) acc[f][q] = 0.0f;
    {
        uint32_t aQ = smem_u32(sq) + (uint32_t)((wm * 16 + (lane & 15)) * (SQR * 2)) + (uint32_t)((lane >> 4) * 16);
        uint32_t bK = smem_u32(sk) + (uint32_t)((wn * 32 + ((lane >> 4) & 1) * 8 + (lane & 7)) * (SQR * 2))
                    + (uint32_t)(((lane >> 3) & 1) * 16);
        #pragma unroll
        for (int ks = 0; ks < 2; ++ks) {
            uint32_t af[4];
            LDSM4(af, aQ + ks * 32);
            #pragma unroll
            for (int half = 0; half < 2; ++half) {
                uint32_t bf[4];
                LDSM4(bf, bK + half * 16 * (SQR * 2) + ks * 32);
                mma_f16(acc[half * 2 + 0], af, &bf[0]);
                mma_f16(acc[half * 2 + 1], af, &bf[2]);
            }
        }
    }

    // ---- fragment-layout bias ----
    const float4* fbp = (const float4*)(fbf + (size_t)(((b & 63) << 4) + h) * 4096 + (size_t)tid * 16);
    float v1r[8], v2r[8];
    #pragma unroll
    for (int f = 0; f < 4; ++f) {
        float4 fv = fbp[f];
        v1r[f * 2]     = acc[f][0] * SCALE + fv.x;
        v1r[f * 2 + 1] = acc[f][1] * SCALE + fv.y;
        v2r[f * 2]     = acc[f][2] * SCALE + fv.z;
        v2r[f * 2 + 1] = acc[f][3] * SCALE + fv.w;
    }

    // ---- per-warp partial softmax ----
    float m1 = -1e30f, m2 = -1e30f;
    #pragma unroll
    for (int j = 0; j < 8; ++j) { m1 = fmaxf(m1, v1r[j]); m2 = fmaxf(m2, v2r[j]); }
    m1 = fmaxf(m1, __shfl_xor_sync(0xffffffffu, m1, 1));
    m1 = fmaxf(m1, __shfl_xor_sync(0xffffffffu, m1, 2));
    m2 = fmaxf(m2, __shfl_xor_sync(0xffffffffu, m2, 1));
    m2 = fmaxf(m2, __shfl_xor_sync(0xffffffffu, m2, 2));
    float s1 = 0.0f, s2 = 0.0f;
    #pragma unroll
    for (int j = 0; j < 8; ++j) {
        v1r[j] = expf(v1r[j] - m1); s1 += v1r[j];
        v2r[j] = expf(v2r[j] - m2); s2 += v2r[j];
    }
    s1 += __shfl_xor_sync(0xffffffffu, s1, 1);
    s1 += __shfl_xor_sync(0xffffffffu, s1, 2);
    s2 += __shfl_xor_sync(0xffffffffu, s2, 1);
    s2 += __shfl_xor_sync(0xffffffffu, s2, 2);
    if ((lane & 3) == 0) {
        red[r1][wn][0] = m1; red[r1][wn][1] = s1;
        red[r2][wn][0] = m2; red[r2][wn][1] = s2;
    }
    __syncthreads();

    float M1 = fmaxf(red[r1][0][0], red[r1][1][0]);
    float S1 = red[r1][0][1] * expf(red[r1][0][0] - M1) + red[r1][1][1] * expf(red[r1][1][0] - M1);
    float fac1 = expf(m1 - M1) / S1;
    float M2 = fmaxf(red[r2][0][0], red[r2][1][0]);
    float S2 = red[r2][0][1] * expf(red[r2][0][0] - M2) + red[r2][1][1] * expf(red[r2][1][0] - M2);
    float fac2 = expf(m2 - M2) / S2;

    // ---- O_partial = P @ V; B from row-major V via ldmatrix.trans ----
    float acc2[4][4];
    #pragma unroll
    for (int nt = 0; nt < 4; ++nt)
        #pragma unroll
        for (int q = 0; q < 4; ++q) acc2[nt][q] = 0.0f;
    {
        uint32_t vb = smem_u32(sv);
        #pragma unroll
        for (int t = 0; t < 2; ++t) {
            uint32_t ap[4];
            __half2 h0 = __floats2half2_rn(v1r[4 * t]     * fac1, v1r[4 * t + 1] * fac1);
            __half2 h1 = __floats2half2_rn(v2r[4 * t]     * fac2, v2r[4 * t + 1] * fac2);
            __half2 h2 = __floats2half2_rn(v1r[4 * t + 2] * fac1, v1r[4 * t + 3] * fac1);
            __half2 h3 = __floats2half2_rn(v2r[4 * t + 2] * fac2, v2r[4 * t + 3] * fac2);
            ap[0] = *(uint32_t*)&h0; ap[1] = *(uint32_t*)&h1;
            ap[2] = *(uint32_t*)&h2; ap[3] = *(uint32_t*)&h3;
            int mb = wn * 32 + t * 16;
            #pragma unroll
            for (int dt = 0; dt < 2; ++dt) {
                uint32_t bf[4];
                uint32_t addr = vb + (uint32_t)(((mb + (lane & 15)) * SQR + dt * 16 + (lane >> 4) * 8) * 2);
                LDSM4T(bf, addr);
                mma_f16(acc2[dt * 2 + 0], ap, &bf[0]);
                mma_f16(acc2[dt * 2 + 1], ap, &bf[2]);
            }
        }
    }

    if (wn == 1) {
        #pragma unroll
        for (int nt = 0; nt < 4; ++nt) {
            int d = nt * 8 + (lane & 3) * 2;
            *(float2*)&pacc[wm][lane >> 2][d]       = make_float2(acc2[nt][0], acc2[nt][1]);
            *(float2*)&pacc[wm][(lane >> 2) + 8][d] = make_float2(acc2[nt][2], acc2[nt][3]);
        }
    }
    __syncthreads();
    if (wn == 0) {
        #pragma unroll
        for (int nt = 0; nt < 4; ++nt) {
            int d = nt * 8 + (lane & 3) * 2;
            float2 p1 = *(const float2*)&pacc[wm][lane >> 2][d];
            float2 p2 = *(const float2*)&pacc[wm][(lane >> 2) + 8][d];
            if (r1 < NWIN)
                *(__half2*)(oh + (size_t)(b * NWIN + r1) * CH + h * HD + d) =
                    __floats2half2_rn(acc2[nt][0] + p1.x, acc2[nt][1] + p1.y);
            if (r2 < NWIN)
                *(__half2*)(oh + (size_t)(b * NWIN + r2) * CH + h * HD + d) =
                    __floats2half2_rn(acc2[nt][2] + p2.x, acc2[nt][3] + p2.y);
        }
    }
}

// ---------------- fused: reverse+roll+residual -> out, LN2 -> yh ----------------
__global__ __launch_bounds__(128)
void fuse2_kernel(const float* __restrict__ x, const __half* __restrict__ projh,
                  const float* __restrict__ gamma, const float* __restrict__ beta,
                  float* __restrict__ out, __half* __restrict__ yh)
{
    int warp = threadIdx.x >> 5, lane = threadIdx.x & 31;
    int tok = blockIdx.x * 4 + warp;
    int b = tok / (HIMG * WIMG);
    int rem = tok - b * (HIMG * WIMG);
    int hp0 = rem / WIMG, wp0 = rem - hp0 * WIMG;
    int hp = hp0 - SSH; if (hp < 0) hp += HIMG;
    int wp = wp0 - SSH; if (wp < 0) wp += WIMG;
    int wh = hp / WS, i = hp - wh * WS;
    int ww = wp / WS, j = wp - ww * WS;
    int src = (b * NW_IMG + wh * 8 + ww) * NWIN + i * WS + j;

    const float* xp = x + (size_t)tok * CH;
    const __half* pp = projh + (size_t)src * CH;
    float* op = out + (size_t)tok * CH;

    float4 a[4];
    float s = 0.0f, sq = 0.0f;
    #pragma unroll
    for (int k = 0; k < 4; ++k) {
        int c = k * 128 + lane * 4;
        a[k] = *(const float4*)(xp + c);
        union { uint2 u; __half hx[4]; } ph;
        ph.u = *(const uint2*)(pp + c);
        a[k].x += __half2float(ph.hx[0]);
        a[k].y += __half2float(ph.hx[1]);
        a[k].z += __half2float(ph.hx[2]);
        a[k].w += __half2float(ph.hx[3]);
        *(float4*)(op + c) = a[k];
        s  += a[k].x + a[k].y + a[k].z + a[k].w;
        sq += a[k].x*a[k].x + a[k].y*a[k].y + a[k].z*a[k].z + a[k].w*a[k].w;
    }
    #pragma unroll
    for (int off = 16; off; off >>= 1) {
        s  += __shfl_xor_sync(0xffffffffu, s, off);
        sq += __shfl_xor_sync(0xffffffffu, sq, off);
    }
    float mean = s * (1.0f / CH);
    float inv = rsqrtf(sq * (1.0f / CH) - mean * mean + 1e-5f);
    __half* yp = yh + (size_t)tok * CH;
    #pragma unroll
    for (int k = 0; k < 4; ++k) {
        int c = k * 128 + lane * 4;
        float4 g4 = *(const float4*)(gamma + c);
        float4 b4 = *(const float4*)(beta + c);
        __half hh[4];
        hh[0] = __float2half_rn((a[k].x - mean) * inv * g4.x + b4.x);
        hh[1] = __float2half_rn((a[k].y - mean) * inv * g4.y + b4.y);
        hh[2] = __float2half_rn((a[k].z - mean) * inv * g4.z + b4.z);
        hh[3] = __float2half_rn((a[k].w - mean) * inv * g4.w + b4.w);
        *(uint2*)(yp + c) = *(uint2*)hh;
    }
}

// ---------------- launcher ----------------
extern "C" void kernel_launch(void* const* d_in, const int* in_sizes, int n_in,
                              void* d_out, int out_size)
{
    const float* x        = (const float*)d_in[0];
    const float* norm1_g  = (const float*)d_in[1];
    const float* norm1_b  = (const float*)d_in[2];
    const float* qkv_w    = (const float*)d_in[3];
    const float* qkv_b    = (const float*)d_in[4];
    const float* rel_tab  = (const float*)d_in[5];
    const float* proj_w   = (const float*)d_in[6];
    const float* proj_b   = (const float*)d_in[7];
    const float* norm2_g  = (const float*)d_in[8];
    const float* norm2_b  = (const float*)d_in[9];
    const float* fc1_w    = (const float*)d_in[10];
    const float* fc1_b    = (const float*)d_in[11];
    const float* fc2_w    = (const float*)d_in[12];
    const float* fc2_b    = (const float*)d_in[13];
    const int*   rel_idx  = (const int*)d_in[14];
    const float* attn_msk = (const float*)d_in[15];
    float* out = (float*)d_out;

    unsigned char *R1, *R2;
    cudaGetSymbolAddress((void**)&R1, g_R1);
    cudaGetSymbolAddress((void**)&R2, g_R2);
    __half *qkvT, *projT, *fc1T, *fc2T;
    cudaGetSymbolAddress((void**)&qkvT, g_qkvT);
    cudaGetSymbolAddress((void**)&projT, g_projT);
    cudaGetSymbolAddress((void**)&fc1T, g_fc1T);
    cudaGetSymbolAddress((void**)&fc2T, g_fc2T);

    __half* qkv   = (__half*)R1;
    __half* projh = (__half*)(R1 + (size_t)MTOK * 3 * CH * 2);
    float* fbf    = (float*)(R1 + (size_t)600 * 1024 * 1024);
    __half* hid   = (__half*)R1;
    __half* act   = (__half*)R2;

    cudaFuncSetAttribute(tgemm<0>, cudaFuncAttributeMaxDynamicSharedMemorySize, TGEMM_SMEM);
    cudaFuncSetAttribute(tgemm<1>, cudaFuncAttributeMaxDynamicSharedMemorySize, TGEMM_SMEM);
    cudaFuncSetAttribute(tgemm<2>, cudaFuncAttributeMaxDynamicSharedMemorySize, TGEMM_SMEM);
    cudaFuncSetAttribute(tgemm<3>, cudaFuncAttributeMaxDynamicSharedMemorySize, TGEMM_SMEM);

    // 0) unified prep
    prep_kernel<<<4096, 256>>>(qkv_w, proj_w, fc1_w, fc2_w, qkvT, projT, fc1T, fc2T,
                               rel_tab, rel_idx, attn_msk, fbf);

    // 1) LN1 + shift + window partition
    ln_kernel<<<MTOK / 4, 128>>>(x, norm1_g, norm1_b, act, 1);

    // 2) QKV GEMM -> fp16
    tgemm<3><<<dim3(3 * CH / 128, MTOK / 128), 256, TGEMM_SMEM>>>(
        act, qkvT, qkv_b, nullptr, qkv, MTOK, 3 * CH, CH);

    // 3) attention
    attn_kernel<<<BN * NHEAD, 256>>>(qkv, fbf, act);

    // 4) proj GEMM -> fp16
    tgemm<3><<<dim3(CH / 128, MTOK / 128), 256, TGEMM_SMEM>>>(
        act, projT, proj_b, nullptr, projh, MTOK, CH, CH);

    // 5+6) reverse + residual -> d_out, fused LN2
    fuse2_kernel<<<MTOK / 4, 128>>>(x, projh, norm2_g, norm2_b, out, act);

    // 7) FC1 + GELU -> fp16 hid
    tgemm<1><<<dim3(HID / 128, MTOK / 128), 256, TGEMM_SMEM>>>(
        act, fc1T, fc1_b, nullptr, hid, MTOK, HID, CH);

    // 8) FC2 + residual into d_out
    tgemm<2><<<dim3(CH / 128, MTOK / 128), 256, TGEMM_SMEM>>>(
        hid, fc2T, fc2_b, out, nullptr, MTOK, CH, HID);

    (void)in_sizes; (void)n_in; (void)out_size;
}

// round 17
// speedup vs baseline: 1.0345x; 1.0111x over previous
#include <cuda_runtime.h>
#include <cuda_fp16.h>
#include <math.h>
#include <stdint.h>

// ---------------- problem constants ----------------
#define BATCH   32
#define HIMG    56
#define WIMG    56
#define CH      512
#define NHEAD   16
#define WS      7
#define SSH     3
#define HD      32
#define NWIN    49
#define NW_IMG  64
#define BN      (BATCH*NW_IMG)      // 2048 windows
#define MTOK    (BN*NWIN)           // 100352 tokens
#define HID     2048
#define SCALE   0.17677669529663687f
#define NN      (NWIN*NWIN)         // 2401

// ---------------- scratch ----------------
__device__ __align__(128) unsigned char g_R1[(size_t)MTOK * HID * 4];
__device__ __align__(128) unsigned char g_R2[(size_t)MTOK * CH * 2];

__device__ __align__(128) __half g_qkvT[3 * CH * CH];
__device__ __align__(128) __half g_projT[CH * CH];
__device__ __align__(128) __half g_fc1T[HID * CH];
__device__ __align__(128) __half g_fc2T[CH * HID];

// ---------------- helpers ----------------
__device__ __forceinline__ uint32_t smem_u32(const void* p) {
    uint32_t a;
    asm("{ .reg .u64 t; cvta.to.shared.u64 t, %1; cvt.u32.u64 %0, t; }" : "=r"(a) : "l"(p));
    return a;
}
#define CP16(dst, src) \
    asm volatile("cp.async.cg.shared.global [%0], [%1], 16;" :: "r"(dst), "l"(src))
#define CPCOMMIT() asm volatile("cp.async.commit_group;" ::: "memory")
#define CPWAIT1()  asm volatile("cp.async.wait_group 1;" ::: "memory")
#define CPWAIT0()  asm volatile("cp.async.wait_group 0;" ::: "memory")

#define LDSM4(r, a) \
    asm volatile("ldmatrix.sync.aligned.m8n8.x4.shared.b16 {%0,%1,%2,%3}, [%4];" \
        : "=r"((r)[0]), "=r"((r)[1]), "=r"((r)[2]), "=r"((r)[3]) : "r"(a))

#define LDSM4T(r, a) \
    asm volatile("ldmatrix.sync.aligned.m8n8.x4.trans.shared.b16 {%0,%1,%2,%3}, [%4];" \
        : "=r"((r)[0]), "=r"((r)[1]), "=r"((r)[2]), "=r"((r)[3]) : "r"(a))

__device__ __forceinline__ void mma_f16(float* c, const uint32_t* a, const uint32_t* b) {
    asm volatile("mma.sync.aligned.m16n8k16.row.col.f32.f16.f16.f32 "
        "{%0,%1,%2,%3}, {%4,%5,%6,%7}, {%8,%9}, {%0,%1,%2,%3};"
        : "+f"(c[0]), "+f"(c[1]), "+f"(c[2]), "+f"(c[3])
        : "r"(a[0]), "r"(a[1]), "r"(a[2]), "r"(a[3]), "r"(b[0]), "r"(b[1]));
}

// ---------------- unified prep kernel ----------------
__device__ __forceinline__ void wsplit_tile(const float* __restrict__ W, __half* __restrict__ oh,
                                            int K, int N, int bx, int by, float (*t)[33])
{
    int n0 = bx * 32, k0 = by * 32;
    int tx = threadIdx.x & 31, ty = threadIdx.x >> 5;
    #pragma unroll
    for (int i = ty; i < 32; i += 8)
        t[i][tx] = W[(size_t)(k0 + i) * N + n0 + tx];
    __syncthreads();
    #pragma unroll
    for (int i = ty; i < 32; i += 8)
        oh[(size_t)(n0 + i) * K + k0 + tx] = __float2half_rn(t[tx][i]);
}

// fused bias in MMA-fragment layout, fp16: fbf[s][wl*16 + f*4 + q]
__global__ __launch_bounds__(256)
void prep_kernel(const float* __restrict__ qkv_w, const float* __restrict__ proj_w,
                 const float* __restrict__ fc1_w, const float* __restrict__ fc2_w,
                 __half* __restrict__ qkvT, __half* __restrict__ projT,
                 __half* __restrict__ fc1T, __half* __restrict__ fc2T,
                 const float* __restrict__ table, const int* __restrict__ relidx,
                 const float* __restrict__ mask, __half* __restrict__ fbf)
{
    __shared__ float t[32][33];
    int id = blockIdx.x;
    if (id < 768) {
        wsplit_tile(qkv_w, qkvT, CH, 3 * CH, id % 48, id / 48, t);
    } else if (id < 1024) {
        int s = id - 768;
        wsplit_tile(proj_w, projT, CH, CH, s % 16, s / 16, t);
    } else if (id < 2048) {
        int s = id - 1024;
        wsplit_tile(fc1_w, fc1T, CH, HID, s % 64, s / 64, t);
    } else if (id < 3072) {
        int s = id - 2048;
        wsplit_tile(fc2_w, fc2T, HID, CH, s % 16, s / 16, t);
    } else {
        int s = id - 3072;
        int wi = s >> 4, h = s & 15;
        const float* mrow = mask + (size_t)wi * NN;
        __half* dst = fbf + (size_t)s * 4096;
        for (int i = threadIdx.x; i < 4096; i += 256) {
            int wl = i >> 4;
            int f = (i >> 2) & 3, q = i & 3;
            int wid = wl >> 5, lane = wl & 31;
            int wm = wid & 3, wn = wid >> 2;
            int r = wm * 16 + (lane >> 2) + (q >= 2 ? 8 : 0);
            int c = wn * 32 + f * 8 + (lane & 3) * 2 + (q & 1);
            float v = -30000.0f;
            if (r < NWIN && c < NWIN)
                v = table[relidx[r * NWIN + c] * NHEAD + h] + mrow[r * NWIN + c];
            dst[i] = __float2half_rn(v);
        }
    }
}

// ---------------- LayerNorm, warp-per-token ----------------
__global__ __launch_bounds__(128)
void ln_kernel(const float* __restrict__ x, const float* __restrict__ gamma,
               const float* __restrict__ beta, __half* __restrict__ oh, int mode)
{
    int warp = threadIdx.x >> 5, lane = threadIdx.x & 31;
    int tok = blockIdx.x * 4 + warp;
    int src;
    if (mode == 1) {
        int w = tok / NWIN, n = tok - w * NWIN;
        int b = w >> 6, wi = w & 63;
        int wh = wi >> 3, ww = wi & 7;
        int i = n / WS, j = n - i * WS;
        int hp = wh * WS + i, wp = ww * WS + j;
        int hs = hp + SSH; if (hs >= HIMG) hs -= HIMG;
        int ws_ = wp + SSH; if (ws_ >= WIMG) ws_ -= WIMG;
        src = b * (HIMG * WIMG) + hs * WIMG + ws_;
    } else {
        src = tok;
    }
    const float* xp = x + (size_t)src * CH;
    float4 v[4];
    float s = 0.0f, sq = 0.0f;
    #pragma unroll
    for (int k = 0; k < 4; ++k) {
        v[k] = *(const float4*)(xp + k * 128 + lane * 4);
        s  += v[k].x + v[k].y + v[k].z + v[k].w;
        sq += v[k].x*v[k].x + v[k].y*v[k].y + v[k].z*v[k].z + v[k].w*v[k].w;
    }
    #pragma unroll
    for (int off = 16; off; off >>= 1) {
        s  += __shfl_xor_sync(0xffffffffu, s, off);
        sq += __shfl_xor_sync(0xffffffffu, sq, off);
    }
    float mean = s * (1.0f / CH);
    float inv = rsqrtf(sq * (1.0f / CH) - mean * mean + 1e-5f);
    __half* op = oh + (size_t)tok * CH;
    #pragma unroll
    for (int k = 0; k < 4; ++k) {
        int c = k * 128 + lane * 4;
        float4 g4 = *(const float4*)(gamma + c);
        float4 b4 = *(const float4*)(beta + c);
        __half hh[4];
        hh[0] = __float2half_rn((v[k].x - mean) * inv * g4.x + b4.x);
        hh[1] = __float2half_rn((v[k].y - mean) * inv * g4.y + b4.y);
        hh[2] = __float2half_rn((v[k].z - mean) * inv * g4.z + b4.z);
        hh[3] = __float2half_rn((v[k].w - mean) * inv * g4.w + b4.w);
        *(uint2*)(op + c) = *(uint2*)hh;
    }
}

// ---------------- fp16 GEMM via mma.sync (R9, f32 accumulate) ----------------
#define OFF_B   16384
#define STG_SZ  32768
#define TGEMM_SMEM (3 * STG_SZ)

template <int EPI>
__global__ void __launch_bounds__(256, 2)
tgemm(const __half* __restrict__ Ah, const __half* __restrict__ Bh,
      const float* __restrict__ bias, float* __restrict__ C,
      __half* __restrict__ Ch, int M, int N, int K)
{
    extern __shared__ __align__(128) char smem[];
    uint32_t sb = smem_u32(smem);
    int tid = threadIdx.x, wid = tid >> 5, lane = tid & 31;
    int m0 = blockIdx.y << 7, n0 = blockIdx.x << 7;
    int wm = wid & 3, wn = wid >> 2;

    int ar = tid >> 1, ac = (tid & 1) * 4;
    const char* gA = (const char*)(Ah + (size_t)(m0 + ar) * K) + ac * 16;
    const char* gB = (const char*)(Bh + (size_t)(n0 + ar) * K) + ac * 16;
    uint32_t sw[4];
    #pragma unroll
    for (int j = 0; j < 4; ++j)
        sw[j] = (uint32_t)(ar * 128 + (((ac + j) ^ (ar & 7)) << 4));

    int arow = wm * 32 + (lane & 15);
    uint32_t aterm = (uint32_t)(arow * 128);
    int axor = arow & 7;
    int ac16 = lane >> 4;
    int brow = wn * 64 + ((lane >> 4) & 1) * 8 + (lane & 7);
    uint32_t bterm = (uint32_t)(brow * 128);
    int bxor = brow & 7;
    int bc16 = (lane >> 3) & 1;

    float acc[2][8][4];
    #pragma unroll
    for (int i = 0; i < 2; ++i)
        #pragma unroll
        for (int j = 0; j < 8; ++j)
            #pragma unroll
            for (int q = 0; q < 4; ++q) acc[i][j][q] = 0.0f;

    const int nch = K >> 6;

    #pragma unroll
    for (int pc = 0; pc < 2; ++pc) {
        uint32_t s = sb + pc * STG_SZ;
        size_t go = (size_t)pc * 128;
        #pragma unroll
        for (int j = 0; j < 4; ++j) {
            CP16(s + sw[j],         gA + go + j * 16);
            CP16(s + OFF_B + sw[j], gB + go + j * 16);
        }
        CPCOMMIT();
    }

    int buf = 0;
    for (int c = 0; c < nch; ++c) {
        if (c + 1 < nch) { CPWAIT1(); } else { CPWAIT0(); }
        __syncthreads();
        if (c + 2 < nch) {
            int b2 = buf + 2; if (b2 >= 3) b2 -= 3;
            uint32_t s = sb + b2 * STG_SZ;
            size_t go = (size_t)(c + 2) * 128;
            #pragma unroll
            for (int j = 0; j < 4; ++j) {
                CP16(s + sw[j],         gA + go + j * 16);
                CP16(s + OFF_B + sw[j], gB + go + j * 16);
            }
            CPCOMMIT();
        } else {
            CPCOMMIT();
        }

        uint32_t sS = sb + buf * STG_SZ;
        #pragma unroll
        for (int k16 = 0; k16 < 4; ++k16) {
            uint32_t ah[2][4];
            uint32_t aoff = aterm + ((uint32_t)((2 * k16 + ac16) ^ axor) << 4);
            LDSM4(ah[0], sS + aoff);
            LDSM4(ah[1], sS + aoff + 2048);
            uint32_t boff = bterm + ((uint32_t)((2 * k16 + bc16) ^ bxor) << 4);
            #pragma unroll
            for (int ng = 0; ng < 4; ++ng) {
                uint32_t bh[4];
                LDSM4(bh, sS + OFF_B + boff + ng * 2048);
                #pragma unroll
                for (int mt = 0; mt < 2; ++mt) {
                    mma_f16(acc[mt][2 * ng],     ah[mt], &bh[0]);
                    mma_f16(acc[mt][2 * ng + 1], ah[mt], &bh[2]);
                }
            }
        }
        if (++buf == 3) buf = 0;
    }

    int r0 = m0 + wm * 32 + (lane >> 2);
    int cb = n0 + wn * 64 + (lane & 3) * 2;
    #pragma unroll
    for (int mt = 0; mt < 2; ++mt) {
        #pragma unroll
        for (int n8 = 0; n8 < 8; ++n8) {
            int col = cb + n8 * 8;
            float2 bv = *(const float2*)(bias + col);
            #pragma unroll
            for (int rt = 0; rt < 2; ++rt) {
                int row = r0 + mt * 16 + rt * 8;
                float vx = acc[mt][n8][rt * 2]     + bv.x;
                float vy = acc[mt][n8][rt * 2 + 1] + bv.y;
                if (EPI == 0) {
                    float2 r = {vx, vy};
                    *(float2*)(C + (size_t)row * N + col) = r;
                } else if (EPI == 1) {
                    float gx = 0.5f * vx * (1.0f + erff(vx * 0.70710678118654752f));
                    float gy = 0.5f * vy * (1.0f + erff(vy * 0.70710678118654752f));
                    __half hh[2];
                    hh[0] = __float2half_rn(gx);
                    hh[1] = __float2half_rn(gy);
                    *(uint32_t*)(Ch + (size_t)row * N + col) = *(uint32_t*)hh;
                } else if (EPI == 2) {
                    float* cp = C + (size_t)row * N + col;
                    float2 old = *(const float2*)cp;
                    float2 r = {vx + old.x, vy + old.y};
                    *(float2*)cp = r;
                } else {
                    __half hh[2];
                    hh[0] = __float2half_rn(vx);
                    hh[1] = __float2half_rn(vy);
                    *(uint32_t*)(Ch + (size_t)row * N + col) = *(uint32_t*)hh;
                }
            }
        }
    }
}

// ---------------- HMMA attention v6: fp16 bias, staged output ----------------
#define SQR 40   // q/k/v row stride (halves) = 80B
__global__ __launch_bounds__(256)
void attn_kernel(const __half* __restrict__ qkv, const __half* __restrict__ fbf,
                 __half* __restrict__ oh)
{
    __shared__ __half sq[64 * SQR], sk[64 * SQR], sv[64 * SQR];
    __shared__ float red[64][2][2];
    __shared__ float pacc[4][16][34];
    __shared__ __half sout[64 * 32];

    int bh = blockIdx.x;
    int b = bh >> 4, h = bh & 15;
    int tid = threadIdx.x, wid = tid >> 5, lane = tid & 31;

    // zero padding rows 49..63 for q, k, v
    for (int idx = tid; idx < 180; idx += 256) {
        int arr = idx / 60, rem = idx - arr * 60;
        int row = 49 + (rem >> 2), c8 = (rem & 3) << 3;
        __half* base = (arr == 0) ? sq : (arr == 1) ? sk : sv;
        *(uint4*)&base[row * SQR + c8] = make_uint4(0, 0, 0, 0);
    }
    // cp.async q/k/v rows
    {
        uint32_t sqa = smem_u32(sq), ska = smem_u32(sk), sva = smem_u32(sv);
        for (int idx = tid; idx < 588; idx += 256) {
            int arr = idx / 196, rem = idx - arr * 196;
            int n = rem >> 2, c8 = (rem & 3) << 3;
            const __half* src = qkv + (size_t)(b * NWIN + n) * (3 * CH) + arr * CH + h * HD + c8;
            uint32_t dst = ((arr == 0) ? sqa : (arr == 1) ? ska : sva)
                         + (uint32_t)((n * SQR + c8) * 2);
            CP16(dst, src);
        }
        CPCOMMIT();
        CPWAIT0();
    }
    __syncthreads();

    int wm = wid & 3, wn = wid >> 2;
    int r1 = wm * 16 + (lane >> 2), r2 = r1 + 8;

    // ---- S = Q @ K^T ----
    float acc[4][4];
    #pragma unroll
    for (int f = 0; f < 4; ++f)
        #pragma unroll
        for (int q = 0; q < 4; ++q) acc[f][q] = 0.0f;
    {
        uint32_t aQ = smem_u32(sq) + (uint32_t)((wm * 16 + (lane & 15)) * (SQR * 2)) + (uint32_t)((lane >> 4) * 16);
        uint32_t bK = smem_u32(sk) + (uint32_t)((wn * 32 + ((lane >> 4) & 1) * 8 + (lane & 7)) * (SQR * 2))
                    + (uint32_t)(((lane >> 3) & 1) * 16);
        #pragma unroll
        for (int ks = 0; ks < 2; ++ks) {
            uint32_t af[4];
            LDSM4(af, aQ + ks * 32);
            #pragma unroll
            for (int half = 0; half < 2; ++half) {
                uint32_t bf[4];
                LDSM4(bf, bK + half * 16 * (SQR * 2) + ks * 32);
                mma_f16(acc[half * 2 + 0], af, &bf[0]);
                mma_f16(acc[half * 2 + 1], af, &bf[2]);
            }
        }
    }

    // ---- fragment-layout fp16 bias: 2 coalesced uint4 loads ----
    float v1r[8], v2r[8];
    {
        const uint4* fbp = (const uint4*)(fbf + (size_t)(((b & 63) << 4) + h) * 4096 + (size_t)tid * 16);
        union { uint4 u; __half2 hx[4]; } b0, b1;
        b0.u = fbp[0]; b1.u = fbp[1];
        #pragma unroll
        for (int f = 0; f < 4; ++f) {
            __half2 lo = (f < 2) ? b0.hx[f * 2]     : b1.hx[(f - 2) * 2];
            __half2 hi = (f < 2) ? b0.hx[f * 2 + 1] : b1.hx[(f - 2) * 2 + 1];
            float2 flo = __half22float2(lo);
            float2 fhi = __half22float2(hi);
            v1r[f * 2]     = acc[f][0] * SCALE + flo.x;
            v1r[f * 2 + 1] = acc[f][1] * SCALE + flo.y;
            v2r[f * 2]     = acc[f][2] * SCALE + fhi.x;
            v2r[f * 2 + 1] = acc[f][3] * SCALE + fhi.y;
        }
    }

    // ---- per-warp partial softmax ----
    float m1 = -1e30f, m2 = -1e30f;
    #pragma unroll
    for (int j = 0; j < 8; ++j) { m1 = fmaxf(m1, v1r[j]); m2 = fmaxf(m2, v2r[j]); }
    m1 = fmaxf(m1, __shfl_xor_sync(0xffffffffu, m1, 1));
    m1 = fmaxf(m1, __shfl_xor_sync(0xffffffffu, m1, 2));
    m2 = fmaxf(m2, __shfl_xor_sync(0xffffffffu, m2, 1));
    m2 = fmaxf(m2, __shfl_xor_sync(0xffffffffu, m2, 2));
    float s1 = 0.0f, s2 = 0.0f;
    #pragma unroll
    for (int j = 0; j < 8; ++j) {
        v1r[j] = expf(v1r[j] - m1); s1 += v1r[j];
        v2r[j] = expf(v2r[j] - m2); s2 += v2r[j];
    }
    s1 += __shfl_xor_sync(0xffffffffu, s1, 1);
    s1 += __shfl_xor_sync(0xffffffffu, s1, 2);
    s2 += __shfl_xor_sync(0xffffffffu, s2, 1);
    s2 += __shfl_xor_sync(0xffffffffu, s2, 2);
    if ((lane & 3) == 0) {
        red[r1][wn][0] = m1; red[r1][wn][1] = s1;
        red[r2][wn][0] = m2; red[r2][wn][1] = s2;
    }
    __syncthreads();

    float M1 = fmaxf(red[r1][0][0], red[r1][1][0]);
    float S1 = red[r1][0][1] * expf(red[r1][0][0] - M1) + red[r1][1][1] * expf(red[r1][1][0] - M1);
    float fac1 = expf(m1 - M1) / S1;
    float M2 = fmaxf(red[r2][0][0], red[r2][1][0]);
    float S2 = red[r2][0][1] * expf(red[r2][0][0] - M2) + red[r2][1][1] * expf(red[r2][1][0] - M2);
    float fac2 = expf(m2 - M2) / S2;

    // ---- O_partial = P @ V (B via ldmatrix.trans on row-major V) ----
    float acc2[4][4];
    #pragma unroll
    for (int nt = 0; nt < 4; ++nt)
        #pragma unroll
        for (int q = 0; q < 4; ++q) acc2[nt][q] = 0.0f;
    {
        uint32_t vb = smem_u32(sv);
        #pragma unroll
        for (int t = 0; t < 2; ++t) {
            uint32_t ap[4];
            __half2 h0 = __floats2half2_rn(v1r[4 * t]     * fac1, v1r[4 * t + 1] * fac1);
            __half2 h1 = __floats2half2_rn(v2r[4 * t]     * fac2, v2r[4 * t + 1] * fac2);
            __half2 h2 = __floats2half2_rn(v1r[4 * t + 2] * fac1, v1r[4 * t + 3] * fac1);
            __half2 h3 = __floats2half2_rn(v2r[4 * t + 2] * fac2, v2r[4 * t + 3] * fac2);
            ap[0] = *(uint32_t*)&h0; ap[1] = *(uint32_t*)&h1;
            ap[2] = *(uint32_t*)&h2; ap[3] = *(uint32_t*)&h3;
            int mb = wn * 32 + t * 16;
            #pragma unroll
            for (int dt = 0; dt < 2; ++dt) {
                uint32_t bf[4];
                uint32_t addr = vb + (uint32_t)(((mb + (lane & 15)) * SQR + dt * 16 + (lane >> 4) * 8) * 2);
                LDSM4T(bf, addr);
                mma_f16(acc2[dt * 2 + 0], ap, &bf[0]);
                mma_f16(acc2[dt * 2 + 1], ap, &bf[2]);
            }
        }
    }

    if (wn == 1) {
        #pragma unroll
        for (int nt = 0; nt < 4; ++nt) {
            int d = nt * 8 + (lane & 3) * 2;
            *(float2*)&pacc[wm][lane >> 2][d]       = make_float2(acc2[nt][0], acc2[nt][1]);
            *(float2*)&pacc[wm][(lane >> 2) + 8][d] = make_float2(acc2[nt][2], acc2[nt][3]);
        }
    }
    __syncthreads();
    if (wn == 0) {
        #pragma unroll
        for (int nt = 0; nt < 4; ++nt) {
            int d = nt * 8 + (lane & 3) * 2;
            float2 p1 = *(const float2*)&pacc[wm][lane >> 2][d];
            float2 p2 = *(const float2*)&pacc[wm][(lane >> 2) + 8][d];
            *(__half2*)&sout[r1 * 32 + d] = __floats2half2_rn(acc2[nt][0] + p1.x, acc2[nt][1] + p1.y);
            *(__half2*)&sout[r2 * 32 + d] = __floats2half2_rn(acc2[nt][2] + p2.x, acc2[nt][3] + p2.y);
        }
    }
    __syncthreads();
    // coalesced output: 196 x 16B
    for (int idx = tid; idx < NWIN * 4; idx += 256) {
        int n = idx >> 2, d8 = (idx & 3) << 3;
        *(uint4*)(oh + (size_t)(b * NWIN + n) * CH + h * HD + d8) = *(const uint4*)&sout[n * 32 + d8];
    }
}

// ---------------- fused: reverse+roll+residual -> out, LN2 -> yh ----------------
__global__ __launch_bounds__(128)
void fuse2_kernel(const float* __restrict__ x, const __half* __restrict__ projh,
                  const float* __restrict__ gamma, const float* __restrict__ beta,
                  float* __restrict__ out, __half* __restrict__ yh)
{
    int warp = threadIdx.x >> 5, lane = threadIdx.x & 31;
    int tok = blockIdx.x * 4 + warp;
    int b = tok / (HIMG * WIMG);
    int rem = tok - b * (HIMG * WIMG);
    int hp0 = rem / WIMG, wp0 = rem - hp0 * WIMG;
    int hp = hp0 - SSH; if (hp < 0) hp += HIMG;
    int wp = wp0 - SSH; if (wp < 0) wp += WIMG;
    int wh = hp / WS, i = hp - wh * WS;
    int ww = wp / WS, j = wp - ww * WS;
    int src = (b * NW_IMG + wh * 8 + ww) * NWIN + i * WS + j;

    const float* xp = x + (size_t)tok * CH;
    const __half* pp = projh + (size_t)src * CH;
    float* op = out + (size_t)tok * CH;

    float4 a[4];
    float s = 0.0f, sq = 0.0f;
    #pragma unroll
    for (int k = 0; k < 4; ++k) {
        int c = k * 128 + lane * 4;
        a[k] = *(const float4*)(xp + c);
        union { uint2 u; __half hx[4]; } ph;
        ph.u = *(const uint2*)(pp + c);
        a[k].x += __half2float(ph.hx[0]);
        a[k].y += __half2float(ph.hx[1]);
        a[k].z += __half2float(ph.hx[2]);
        a[k].w += __half2float(ph.hx[3]);
        *(float4*)(op + c) = a[k];
        s  += a[k].x + a[k].y + a[k].z + a[k].w;
        sq += a[k].x*a[k].x + a[k].y*a[k].y + a[k].z*a[k].z + a[k].w*a[k].w;
    }
    #pragma unroll
    for (int off = 16; off; off >>= 1) {
        s  += __shfl_xor_sync(0xffffffffu, s, off);
        sq += __shfl_xor_sync(0xffffffffu, sq, off);
    }
    float mean = s * (1.0f / CH);
    float inv = rsqrtf(sq * (1.0f / CH) - mean * mean + 1e-5f);
    __half* yp = yh + (size_t)tok * CH;
    #pragma unroll
    for (int k = 0; k < 4; ++k) {
        int c = k * 128 + lane * 4;
        float4 g4 = *(const float4*)(gamma + c);
        float4 b4 = *(const float4*)(beta + c);
        __half hh[4];
        hh[0] = __float2half_rn((a[k].x - mean) * inv * g4.x + b4.x);
        hh[1] = __float2half_rn((a[k].y - mean) * inv * g4.y + b4.y);
        hh[2] = __float2half_rn((a[k].z - mean) * inv * g4.z + b4.z);
        hh[3] = __float2half_rn((a[k].w - mean) * inv * g4.w + b4.w);
        *(uint2*)(yp + c) = *(uint2*)hh;
    }
}

// ---------------- launcher ----------------
extern "C" void kernel_launch(void* const* d_in, const int* in_sizes, int n_in,
                              void* d_out, int out_size)
{
    const float* x        = (const float*)d_in[0];
    const float* norm1_g  = (const float*)d_in[1];
    const float* norm1_b  = (const float*)d_in[2];
    const float* qkv_w    = (const float*)d_in[3];
    const float* qkv_b    = (const float*)d_in[4];
    const float* rel_tab  = (const float*)d_in[5];
    const float* proj_w   = (const float*)d_in[6];
    const float* proj_b   = (const float*)d_in[7];
    const float* norm2_g  = (const float*)d_in[8];
    const float* norm2_b  = (const float*)d_in[9];
    const float* fc1_w    = (const float*)d_in[10];
    const float* fc1_b    = (const float*)d_in[11];
    const float* fc2_w    = (const float*)d_in[12];
    const float* fc2_b    = (const float*)d_in[13];
    const int*   rel_idx  = (const int*)d_in[14];
    const float* attn_msk = (const float*)d_in[15];
    float* out = (float*)d_out;

    unsigned char *R1, *R2;
    cudaGetSymbolAddress((void**)&R1, g_R1);
    cudaGetSymbolAddress((void**)&R2, g_R2);
    __half *qkvT, *projT, *fc1T, *fc2T;
    cudaGetSymbolAddress((void**)&qkvT, g_qkvT);
    cudaGetSymbolAddress((void**)&projT, g_projT);
    cudaGetSymbolAddress((void**)&fc1T, g_fc1T);
    cudaGetSymbolAddress((void**)&fc2T, g_fc2T);

    __half* qkv   = (__half*)R1;
    __half* projh = (__half*)(R1 + (size_t)MTOK * 3 * CH * 2);
    __half* fbf   = (__half*)(R1 + (size_t)600 * 1024 * 1024);   // 8.4MB fp16 fragment bias
    __half* hid   = (__half*)R1;
    __half* act   = (__half*)R2;

    cudaFuncSetAttribute(tgemm<0>, cudaFuncAttributeMaxDynamicSharedMemorySize, TGEMM_SMEM);
    cudaFuncSetAttribute(tgemm<1>, cudaFuncAttributeMaxDynamicSharedMemorySize, TGEMM_SMEM);
    cudaFuncSetAttribute(tgemm<2>, cudaFuncAttributeMaxDynamicSharedMemorySize, TGEMM_SMEM);
    cudaFuncSetAttribute(tgemm<3>, cudaFuncAttributeMaxDynamicSharedMemorySize, TGEMM_SMEM);

    // 0) unified prep
    prep_kernel<<<4096, 256>>>(qkv_w, proj_w, fc1_w, fc2_w, qkvT, projT, fc1T, fc2T,
                               rel_tab, rel_idx, attn_msk, fbf);

    // 1) LN1 + shift + window partition
    ln_kernel<<<MTOK / 4, 128>>>(x, norm1_g, norm1_b, act, 1);

    // 2) QKV GEMM -> fp16
    tgemm<3><<<dim3(3 * CH / 128, MTOK / 128), 256, TGEMM_SMEM>>>(
        act, qkvT, qkv_b, nullptr, qkv, MTOK, 3 * CH, CH);

    // 3) attention
    attn_kernel<<<BN * NHEAD, 256>>>(qkv, fbf, act);

    // 4) proj GEMM -> fp16
    tgemm<3><<<dim3(CH / 128, MTOK / 128), 256, TGEMM_SMEM>>>(
        act, projT, proj_b, nullptr, projh, MTOK, CH, CH);

    // 5+6) reverse + residual -> d_out, fused LN2
    fuse2_kernel<<<MTOK / 4, 128>>>(x, projh, norm2_g, norm2_b, out, act);

    // 7) FC1 + GELU -> fp16 hid
    tgemm<1><<<dim3(HID / 128, MTOK / 128), 256, TGEMM_SMEM>>>(
        act, fc1T, fc1_b, nullptr, hid, MTOK, HID, CH);

    // 8) FC2 + residual into d_out
    tgemm<2><<<dim3(CH / 128, MTOK / 128), 256, TGEMM_SMEM>>>(
        hid, fc2T, fc2_b, out, nullptr, MTOK, CH, HID);

    (void)in_sizes; (void)n_in; (void)out_size;
}